// round 9
// baseline (speedup 1.0000x reference)
#include <cuda_runtime.h>
#include <math_constants.h>

// ---------------- problem constants ----------------
constexpr int   kD     = 2048;
constexpr int   kF     = 2048;
constexpr int   kE     = 8;
constexpr int   kT     = 4096;       // tokens = 4*1024
constexpr int   kSlots = 2 * kT;     // top-2 assignments
constexpr int   kBM    = 64;
constexpr float kAlpha = 1.702f;
constexpr float kLimit = 7.0f;
constexpr float kAux   = 0.01f;

// ---------------- device scratch (no allocations allowed) ----------------
__device__ int   g_counts[kE];
__device__ int   g_sid[kE * kT];                 // slot id = token*2 + k
__device__ float g_sw [kE * kT];                 // routing weight for slot
__device__ float g_probs[kT * kE];               // full softmax probs
__device__ float g_act[(size_t)kSlots * kF];     // 64 MB: activated hidden
__device__ float g_partial[(size_t)kSlots * kD]; // 64 MB: weighted expert out

// ---------------- kernel 0: reset counters (graph replays!) --------------
__global__ void moe_init_kernel() {
    if (threadIdx.x < kE) g_counts[threadIdx.x] = 0;
}

// ---------------- kernel 1: router (one warp per token) ------------------
__global__ void moe_router_kernel(const float* __restrict__ x,
                                  const float* __restrict__ rw,
                                  const float* __restrict__ rb) {
    int gw   = (blockIdx.x * blockDim.x + threadIdx.x) >> 5;
    int lane = threadIdx.x & 31;
    if (gw >= kT) return;

    const float* xr = x + (size_t)gw * kD;
    float acc[kE];
#pragma unroll
    for (int e = 0; e < kE; ++e) acc[e] = 0.f;

    for (int d = lane; d < kD; d += 32) {
        float xv = xr[d];
        const float* w = rw + (size_t)d * kE;
#pragma unroll
        for (int e = 0; e < kE; ++e) acc[e] = fmaf(xv, w[e], acc[e]);
    }
#pragma unroll
    for (int e = 0; e < kE; ++e) {
#pragma unroll
        for (int off = 16; off > 0; off >>= 1)
            acc[e] += __shfl_xor_sync(0xffffffffu, acc[e], off);
    }

    if (lane == 0) {
        float lg[kE];
#pragma unroll
        for (int e = 0; e < kE; ++e) lg[e] = acc[e] + rb[e];

        // top-2 (ties -> lowest index, matching lax.top_k)
        int i0 = 0; float l0 = lg[0];
#pragma unroll
        for (int e = 1; e < kE; ++e) if (lg[e] > l0) { l0 = lg[e]; i0 = e; }
        int i1 = -1; float l1 = -CUDART_INF_F;
#pragma unroll
        for (int e = 0; e < kE; ++e)
            if (e != i0 && lg[e] > l1) { l1 = lg[e]; i1 = e; }

        // full softmax probs (needed for aux loss)
        float p[kE]; float s = 0.f;
#pragma unroll
        for (int e = 0; e < kE; ++e) { p[e] = __expf(lg[e] - l0); s += p[e]; }
        float inv = 1.f / s;
#pragma unroll
        for (int e = 0; e < kE; ++e) g_probs[gw * kE + e] = p[e] * inv;

        // routing weights = softmax([l0, l1])
        float r  = __expf(l1 - l0);
        float w0 = 1.f / (1.f + r);
        float w1 = r * w0;

        int s0 = atomicAdd(&g_counts[i0], 1);
        g_sid[i0 * kT + s0] = gw * 2;     g_sw[i0 * kT + s0] = w0;
        int s1 = atomicAdd(&g_counts[i1], 1);
        g_sid[i1 * kT + s1] = gw * 2 + 1; g_sw[i1 * kT + s1] = w1;
    }
}

// ---------------- kernel 2: gathered gate_up GEMM + GLU activation -------
// Tile: 64 rows (assignments) x 64 act-cols (128 weight cols) x K-step 32.
// 256 threads, each owns 4 rows x 4 act-cols (gate+up accumulators).
__global__ void __launch_bounds__(256)
moe_gate_up_kernel(const float* __restrict__ x,
                   const float* __restrict__ wgu,   // [E][D][2F]
                   const float* __restrict__ bgu) { // [E][2F]
    const int e   = blockIdx.y >> 6;
    const int m0  = (blockIdx.y & 63) * kBM;
    const int cnt = g_counts[e];
    if (m0 >= cnt) return;
    const int f0 = blockIdx.x * 64;

    __shared__ __align__(16) float As[32][68];
    __shared__ __align__(16) float Bs[32][128];
    __shared__ int s_sid[kBM];

    const int tid = threadIdx.x;
    if (tid < kBM) {
        int m = m0 + tid;
        s_sid[tid] = (m < cnt) ? g_sid[e * kT + m] : -1;
    }
    __syncthreads();

    // A loader: row = tid&63, k-chunk = (tid>>6)*4 (and +16)
    const int ra = tid & 63;
    const int ka = (tid >> 6) * 4;
    int sidA = s_sid[ra];
    const float* apA = x + (size_t)(sidA < 0 ? 0 : (sidA >> 1)) * kD + ka;

    // B loader: row = (tid>>5) + 8*i, col = (tid&31)*4
    const int rb0 = tid >> 5;
    const int cb  = (tid & 31) * 4;
    const float* bp = wgu + (size_t)e * kD * (2 * kF)
                          + (size_t)rb0 * (2 * kF) + (size_t)f0 * 2 + cb;

    const int ty = tid >> 4;
    const int tx = tid & 15;

    float accg[4][4], accu[4][4];
#pragma unroll
    for (int i = 0; i < 4; ++i)
#pragma unroll
        for (int j = 0; j < 4; ++j) { accg[i][j] = 0.f; accu[i][j] = 0.f; }

    for (int k0 = 0; k0 < kD; k0 += 32) {
        float4 a0 = *(const float4*)(apA + k0);
        float4 a1 = *(const float4*)(apA + k0 + 16);
        float4 b0 = *(const float4*)(bp + (size_t)(k0 +  0) * (2 * kF));
        float4 b1 = *(const float4*)(bp + (size_t)(k0 +  8) * (2 * kF));
        float4 b2 = *(const float4*)(bp + (size_t)(k0 + 16) * (2 * kF));
        float4 b3 = *(const float4*)(bp + (size_t)(k0 + 24) * (2 * kF));
        __syncthreads();
        As[ka + 0][ra] = a0.x; As[ka + 1][ra] = a0.y;
        As[ka + 2][ra] = a0.z; As[ka + 3][ra] = a0.w;
        As[ka + 16][ra] = a1.x; As[ka + 17][ra] = a1.y;
        As[ka + 18][ra] = a1.z; As[ka + 19][ra] = a1.w;
        *(float4*)&Bs[rb0     ][cb] = b0;
        *(float4*)&Bs[rb0 +  8][cb] = b1;
        *(float4*)&Bs[rb0 + 16][cb] = b2;
        *(float4*)&Bs[rb0 + 24][cb] = b3;
        __syncthreads();

#pragma unroll
        for (int kk = 0; kk < 32; ++kk) {
            float4 av  = *(const float4*)&As[kk][ty * 4];
            float4 bv0 = *(const float4*)&Bs[kk][tx * 8];
            float4 bv1 = *(const float4*)&Bs[kk][tx * 8 + 4];
            float a[4]   = {av.x, av.y, av.z, av.w};
            float bgv[4] = {bv0.x, bv0.z, bv1.x, bv1.z};
            float buv[4] = {bv0.y, bv0.w, bv1.y, bv1.w};
#pragma unroll
            for (int i = 0; i < 4; ++i)
#pragma unroll
                for (int j = 0; j < 4; ++j) {
                    accg[i][j] = fmaf(a[i], bgv[j], accg[i][j]);
                    accu[i][j] = fmaf(a[i], buv[j], accu[i][j]);
                }
        }
    }

    // epilogue: bias + clamp + SiLU-GLU, store to act[slot]
#pragma unroll
    for (int i = 0; i < 4; ++i) {
        int r = ty * 4 + i;
        int sid = s_sid[r];
        if (sid < 0) continue;
        float4 o;
        float* ov = (float*)&o;
#pragma unroll
        for (int j = 0; j < 4; ++j) {
            int f = f0 + tx * 4 + j;
            float g = accg[i][j] + bgu[e * (2 * kF) + 2 * f];
            float u = accu[i][j] + bgu[e * (2 * kF) + 2 * f + 1];
            g = fminf(g, kLimit);
            u = fminf(fmaxf(u, -kLimit), kLimit);
            float sig = 1.f / (1.f + __expf(-kAlpha * g));
            ov[j] = (u + 1.f) * (g * sig);
        }
        *(float4*)(g_act + (size_t)sid * kF + f0 + tx * 4) = o;
    }
}

// ---------------- kernel 3: gathered down GEMM (+bias, x routing weight) -
// Tile: 64 rows x 128 out-cols x K-step 32; each thread 4 rows x 8 cols.
__global__ void __launch_bounds__(256)
moe_down_kernel(const float* __restrict__ wdn,   // [E][F][D]
                const float* __restrict__ bdn) { // [E][D]
    const int e   = blockIdx.y >> 6;
    const int m0  = (blockIdx.y & 63) * kBM;
    const int cnt = g_counts[e];
    if (m0 >= cnt) return;
    const int n0 = blockIdx.x * 128;

    __shared__ __align__(16) float As[32][68];
    __shared__ __align__(16) float Bs[32][128];
    __shared__ int   s_sid[kBM];
    __shared__ float s_w[kBM];

    const int tid = threadIdx.x;
    if (tid < kBM) {
        int m = m0 + tid;
        bool v = (m < cnt);
        s_sid[tid] = v ? g_sid[e * kT + m] : -1;
        s_w[tid]   = v ? g_sw [e * kT + m] : 0.f;
    }
    __syncthreads();

    const int ra = tid & 63;
    const int ka = (tid >> 6) * 4;
    int sidA = s_sid[ra];
    const float* apA = g_act + (size_t)(sidA < 0 ? 0 : sidA) * kF + ka;

    const int rb0 = tid >> 5;
    const int cb  = (tid & 31) * 4;
    const float* bp = wdn + (size_t)e * kF * kD + (size_t)rb0 * kD + n0 + cb;

    const int ty = tid >> 4;
    const int tx = tid & 15;

    float acc[4][8];
#pragma unroll
    for (int i = 0; i < 4; ++i)
#pragma unroll
        for (int j = 0; j < 8; ++j) acc[i][j] = 0.f;

    for (int k0 = 0; k0 < kF; k0 += 32) {
        float4 a0 = *(const float4*)(apA + k0);
        float4 a1 = *(const float4*)(apA + k0 + 16);
        float4 b0 = *(const float4*)(bp + (size_t)(k0 +  0) * kD);
        float4 b1 = *(const float4*)(bp + (size_t)(k0 +  8) * kD);
        float4 b2 = *(const float4*)(bp + (size_t)(k0 + 16) * kD);
        float4 b3 = *(const float4*)(bp + (size_t)(k0 + 24) * kD);
        __syncthreads();
        As[ka + 0][ra] = a0.x; As[ka + 1][ra] = a0.y;
        As[ka + 2][ra] = a0.z; As[ka + 3][ra] = a0.w;
        As[ka + 16][ra] = a1.x; As[ka + 17][ra] = a1.y;
        As[ka + 18][ra] = a1.z; As[ka + 19][ra] = a1.w;
        *(float4*)&Bs[rb0     ][cb] = b0;
        *(float4*)&Bs[rb0 +  8][cb] = b1;
        *(float4*)&Bs[rb0 + 16][cb] = b2;
        *(float4*)&Bs[rb0 + 24][cb] = b3;
        __syncthreads();

#pragma unroll
        for (int kk = 0; kk < 32; ++kk) {
            float4 av  = *(const float4*)&As[kk][ty * 4];
            float4 bv0 = *(const float4*)&Bs[kk][tx * 8];
            float4 bv1 = *(const float4*)&Bs[kk][tx * 8 + 4];
            float a[4] = {av.x, av.y, av.z, av.w};
            float b[8] = {bv0.x, bv0.y, bv0.z, bv0.w,
                          bv1.x, bv1.y, bv1.z, bv1.w};
#pragma unroll
            for (int i = 0; i < 4; ++i)
#pragma unroll
                for (int j = 0; j < 8; ++j)
                    acc[i][j] = fmaf(a[i], b[j], acc[i][j]);
        }
    }

#pragma unroll
    for (int i = 0; i < 4; ++i) {
        int r = ty * 4 + i;
        int sid = s_sid[r];
        if (sid < 0) continue;
        float w = s_w[r];
        float4 o0, o1;
        float* ov0 = (float*)&o0;
        float* ov1 = (float*)&o1;
#pragma unroll
        for (int j = 0; j < 4; ++j) {
            int c = n0 + tx * 8 + j;
            ov0[j] = w * (acc[i][j] + bdn[e * kD + c]);
        }
#pragma unroll
        for (int j = 4; j < 8; ++j) {
            int c = n0 + tx * 8 + j;
            ov1[j - 4] = w * (acc[i][j] + bdn[e * kD + c]);
        }
        float* dst = g_partial + (size_t)sid * kD + n0 + tx * 8;
        *(float4*)dst       = o0;
        *(float4*)(dst + 4) = o1;
    }
}

// ---------------- kernel 4: combine the two expert partials per token ----
__global__ void moe_combine_kernel(float* __restrict__ out) {
    size_t idx = (size_t)blockIdx.x * blockDim.x + threadIdx.x; // float4 idx
    // total float4 = kT * kD / 4 = 2,097,152 (grid sized exactly)
    size_t t = idx >> 9;          // / (kD/4)
    size_t c = idx & 511;         // % (kD/4)
    const float4* p = (const float4*)g_partial;
    float4 a = p[(2 * t) * 512 + c];
    float4 b = p[(2 * t + 1) * 512 + c];
    float4 o = make_float4(a.x + b.x, a.y + b.y, a.z + b.z, a.w + b.w);
    ((float4*)out)[idx] = o;
}

// ---------------- kernel 5: expert loads + aux loss (deterministic) ------
__global__ void moe_loss_kernel(float* __restrict__ out_tail) {
    __shared__ float red[256];
    __shared__ float means[kE];
    float s[kE];
#pragma unroll
    for (int e = 0; e < kE; ++e) s[e] = 0.f;
    for (int t = threadIdx.x; t < kT; t += 256) {
        const float* p = g_probs + (size_t)t * kE;
#pragma unroll
        for (int e = 0; e < kE; ++e) s[e] += p[e];
    }
    for (int e = 0; e < kE; ++e) {
        red[threadIdx.x] = s[e];
        __syncthreads();
        for (int off = 128; off > 0; off >>= 1) {
            if (threadIdx.x < off) red[threadIdx.x] += red[threadIdx.x + off];
            __syncthreads();
        }
        if (threadIdx.x == 0) means[e] = red[0] / (float)kT;
        __syncthreads();
    }
    if (threadIdx.x == 0) {
        float loss = 0.f;
        for (int e = 0; e < kE; ++e) {
            float frac = (float)g_counts[e] / (float)(kT * 2);
            out_tail[e] = frac;                 // expert_loads
            loss += frac * means[e];
        }
        out_tail[kE] = kAux * (float)kE * loss; // load_balancing_loss
    }
}

// ---------------- launch ----------------
extern "C" void kernel_launch(void* const* d_in, const int* in_sizes, int n_in,
                              void* d_out, int out_size) {
    const float* x   = (const float*)d_in[0];
    const float* rw  = (const float*)d_in[1];
    const float* rb  = (const float*)d_in[2];
    const float* wgu = (const float*)d_in[3];
    const float* bgu = (const float*)d_in[4];
    const float* wdn = (const float*)d_in[5];
    const float* bdn = (const float*)d_in[6];
    float* out = (float*)d_out;

    moe_init_kernel<<<1, 32>>>();
    moe_router_kernel<<<(kT * 32) / 256, 256>>>(x, rw, rb);

    // worst case: one expert owns all 4096 tokens -> 64 M-tiles per expert
    dim3 g1(kF / 64, kE * 64);   // (32, 512)
    moe_gate_up_kernel<<<g1, 256>>>(x, wgu, bgu);

    dim3 g2(kD / 128, kE * 64);  // (16, 512)
    moe_down_kernel<<<g2, 256>>>(wdn, bdn);

    moe_combine_kernel<<<(kT * kD / 4) / 256, 256>>>(out);
    moe_loss_kernel<<<1, 256>>>(out + (size_t)kT * kD);
}

// round 10
// speedup vs baseline: 1.0030x; 1.0030x over previous
#include <cuda_runtime.h>
#include <math_constants.h>

// ---------------- problem constants ----------------
constexpr int   kD     = 2048;
constexpr int   kF     = 2048;
constexpr int   kE     = 8;
constexpr int   kT     = 4096;       // tokens = 4*1024
constexpr int   kSlots = 2 * kT;     // top-2 assignments
constexpr int   kBM    = 64;
constexpr float kAlpha = 1.702f;
constexpr float kLimit = 7.0f;
constexpr float kAux   = 0.01f;

// ---------------- device scratch (no allocations allowed) ----------------
__device__ int   g_counts[kE];
__device__ int   g_sid[kE * kT];                 // slot id = token*2 + k
__device__ float g_sw [kE * kT];                 // routing weight for slot
__device__ float g_probs[kT * kE];               // full softmax probs
__device__ float g_act[(size_t)kSlots * kF];     // 64 MB: activated hidden
__device__ float g_partial[(size_t)kSlots * kD]; // 64 MB: weighted expert out

// ---------------- kernel 0: reset counters (graph replays!) --------------
__global__ void moe_init_kernel() {
    if (threadIdx.x < kE) g_counts[threadIdx.x] = 0;
}

// ---------------- kernel 1: router (one warp per token) ------------------
__global__ void moe_router_kernel(const float* __restrict__ x,
                                  const float* __restrict__ rw,
                                  const float* __restrict__ rb) {
    int gw   = (blockIdx.x * blockDim.x + threadIdx.x) >> 5;
    int lane = threadIdx.x & 31;
    if (gw >= kT) return;

    const float* xr = x + (size_t)gw * kD;
    float acc[kE];
#pragma unroll
    for (int e = 0; e < kE; ++e) acc[e] = 0.f;

    for (int d = lane; d < kD; d += 32) {
        float xv = xr[d];
        const float* w = rw + (size_t)d * kE;
#pragma unroll
        for (int e = 0; e < kE; ++e) acc[e] = fmaf(xv, w[e], acc[e]);
    }
#pragma unroll
    for (int e = 0; e < kE; ++e) {
#pragma unroll
        for (int off = 16; off > 0; off >>= 1)
            acc[e] += __shfl_xor_sync(0xffffffffu, acc[e], off);
    }

    if (lane == 0) {
        float lg[kE];
#pragma unroll
        for (int e = 0; e < kE; ++e) lg[e] = acc[e] + rb[e];

        // top-2 (ties -> lowest index, matching lax.top_k)
        int i0 = 0; float l0 = lg[0];
#pragma unroll
        for (int e = 1; e < kE; ++e) if (lg[e] > l0) { l0 = lg[e]; i0 = e; }
        int i1 = -1; float l1 = -CUDART_INF_F;
#pragma unroll
        for (int e = 0; e < kE; ++e)
            if (e != i0 && lg[e] > l1) { l1 = lg[e]; i1 = e; }

        // full softmax probs (needed for aux loss)
        float p[kE]; float s = 0.f;
#pragma unroll
        for (int e = 0; e < kE; ++e) { p[e] = __expf(lg[e] - l0); s += p[e]; }
        float inv = 1.f / s;
#pragma unroll
        for (int e = 0; e < kE; ++e) g_probs[gw * kE + e] = p[e] * inv;

        // routing weights = softmax([l0, l1])
        float r  = __expf(l1 - l0);
        float w0 = 1.f / (1.f + r);
        float w1 = r * w0;

        int s0 = atomicAdd(&g_counts[i0], 1);
        g_sid[i0 * kT + s0] = gw * 2;     g_sw[i0 * kT + s0] = w0;
        int s1 = atomicAdd(&g_counts[i1], 1);
        g_sid[i1 * kT + s1] = gw * 2 + 1; g_sw[i1 * kT + s1] = w1;
    }
}

// ---------------- kernel 2: gathered gate_up GEMM + GLU activation -------
// Tile: 64 rows (assignments) x 64 act-cols (128 weight cols) x K-step 32.
// 256 threads, each owns 4 rows x 4 act-cols (gate+up accumulators).
__global__ void __launch_bounds__(256)
moe_gate_up_kernel(const float* __restrict__ x,
                   const float* __restrict__ wgu,   // [E][D][2F]
                   const float* __restrict__ bgu) { // [E][2F]
    const int e   = blockIdx.y >> 6;
    const int m0  = (blockIdx.y & 63) * kBM;
    const int cnt = g_counts[e];
    if (m0 >= cnt) return;
    const int f0 = blockIdx.x * 64;

    __shared__ __align__(16) float As[32][68];
    __shared__ __align__(16) float Bs[32][128];
    __shared__ int s_sid[kBM];

    const int tid = threadIdx.x;
    if (tid < kBM) {
        int m = m0 + tid;
        s_sid[tid] = (m < cnt) ? g_sid[e * kT + m] : -1;
    }
    __syncthreads();

    // A loader: row = tid&63, k-chunk = (tid>>6)*4 (and +16)
    const int ra = tid & 63;
    const int ka = (tid >> 6) * 4;
    int sidA = s_sid[ra];
    const float* apA = x + (size_t)(sidA < 0 ? 0 : (sidA >> 1)) * kD + ka;

    // B loader: row = (tid>>5) + 8*i, col = (tid&31)*4
    const int rb0 = tid >> 5;
    const int cb  = (tid & 31) * 4;
    const float* bp = wgu + (size_t)e * kD * (2 * kF)
                          + (size_t)rb0 * (2 * kF) + (size_t)f0 * 2 + cb;

    const int ty = tid >> 4;
    const int tx = tid & 15;

    float accg[4][4], accu[4][4];
#pragma unroll
    for (int i = 0; i < 4; ++i)
#pragma unroll
        for (int j = 0; j < 4; ++j) { accg[i][j] = 0.f; accu[i][j] = 0.f; }

    for (int k0 = 0; k0 < kD; k0 += 32) {
        float4 a0 = *(const float4*)(apA + k0);
        float4 a1 = *(const float4*)(apA + k0 + 16);
        float4 b0 = *(const float4*)(bp + (size_t)(k0 +  0) * (2 * kF));
        float4 b1 = *(const float4*)(bp + (size_t)(k0 +  8) * (2 * kF));
        float4 b2 = *(const float4*)(bp + (size_t)(k0 + 16) * (2 * kF));
        float4 b3 = *(const float4*)(bp + (size_t)(k0 + 24) * (2 * kF));
        __syncthreads();
        As[ka + 0][ra] = a0.x; As[ka + 1][ra] = a0.y;
        As[ka + 2][ra] = a0.z; As[ka + 3][ra] = a0.w;
        As[ka + 16][ra] = a1.x; As[ka + 17][ra] = a1.y;
        As[ka + 18][ra] = a1.z; As[ka + 19][ra] = a1.w;
        *(float4*)&Bs[rb0     ][cb] = b0;
        *(float4*)&Bs[rb0 +  8][cb] = b1;
        *(float4*)&Bs[rb0 + 16][cb] = b2;
        *(float4*)&Bs[rb0 + 24][cb] = b3;
        __syncthreads();

#pragma unroll
        for (int kk = 0; kk < 32; ++kk) {
            float4 av  = *(const float4*)&As[kk][ty * 4];
            float4 bv0 = *(const float4*)&Bs[kk][tx * 8];
            float4 bv1 = *(const float4*)&Bs[kk][tx * 8 + 4];
            float a[4]   = {av.x, av.y, av.z, av.w};
            float bgv[4] = {bv0.x, bv0.z, bv1.x, bv1.z};
            float buv[4] = {bv0.y, bv0.w, bv1.y, bv1.w};
#pragma unroll
            for (int i = 0; i < 4; ++i)
#pragma unroll
                for (int j = 0; j < 4; ++j) {
                    accg[i][j] = fmaf(a[i], bgv[j], accg[i][j]);
                    accu[i][j] = fmaf(a[i], buv[j], accu[i][j]);
                }
        }
    }

    // epilogue: bias + clamp + SiLU-GLU, store to act[slot]
#pragma unroll
    for (int i = 0; i < 4; ++i) {
        int r = ty * 4 + i;
        int sid = s_sid[r];
        if (sid < 0) continue;
        float4 o;
        float* ov = (float*)&o;
#pragma unroll
        for (int j = 0; j < 4; ++j) {
            int f = f0 + tx * 4 + j;
            float g = accg[i][j] + bgu[e * (2 * kF) + 2 * f];
            float u = accu[i][j] + bgu[e * (2 * kF) + 2 * f + 1];
            g = fminf(g, kLimit);
            u = fminf(fmaxf(u, -kLimit), kLimit);
            float sig = 1.f / (1.f + __expf(-kAlpha * g));
            ov[j] = (u + 1.f) * (g * sig);
        }
        *(float4*)(g_act + (size_t)sid * kF + f0 + tx * 4) = o;
    }
}

// ---------------- kernel 3: gathered down GEMM (+bias, x routing weight) -
// Tile: 64 rows x 128 out-cols x K-step 32; each thread 4 rows x 8 cols.
__global__ void __launch_bounds__(256)
moe_down_kernel(const float* __restrict__ wdn,   // [E][F][D]
                const float* __restrict__ bdn) { // [E][D]
    const int e   = blockIdx.y >> 6;
    const int m0  = (blockIdx.y & 63) * kBM;
    const int cnt = g_counts[e];
    if (m0 >= cnt) return;
    const int n0 = blockIdx.x * 128;

    __shared__ __align__(16) float As[32][68];
    __shared__ __align__(16) float Bs[32][128];
    __shared__ int   s_sid[kBM];
    __shared__ float s_w[kBM];

    const int tid = threadIdx.x;
    if (tid < kBM) {
        int m = m0 + tid;
        bool v = (m < cnt);
        s_sid[tid] = v ? g_sid[e * kT + m] : -1;
        s_w[tid]   = v ? g_sw [e * kT + m] : 0.f;
    }
    __syncthreads();

    const int ra = tid & 63;
    const int ka = (tid >> 6) * 4;
    int sidA = s_sid[ra];
    const float* apA = g_act + (size_t)(sidA < 0 ? 0 : sidA) * kF + ka;

    const int rb0 = tid >> 5;
    const int cb  = (tid & 31) * 4;
    const float* bp = wdn + (size_t)e * kF * kD + (size_t)rb0 * kD + n0 + cb;

    const int ty = tid >> 4;
    const int tx = tid & 15;

    float acc[4][8];
#pragma unroll
    for (int i = 0; i < 4; ++i)
#pragma unroll
        for (int j = 0; j < 8; ++j) acc[i][j] = 0.f;

    for (int k0 = 0; k0 < kF; k0 += 32) {
        float4 a0 = *(const float4*)(apA + k0);
        float4 a1 = *(const float4*)(apA + k0 + 16);
        float4 b0 = *(const float4*)(bp + (size_t)(k0 +  0) * kD);
        float4 b1 = *(const float4*)(bp + (size_t)(k0 +  8) * kD);
        float4 b2 = *(const float4*)(bp + (size_t)(k0 + 16) * kD);
        float4 b3 = *(const float4*)(bp + (size_t)(k0 + 24) * kD);
        __syncthreads();
        As[ka + 0][ra] = a0.x; As[ka + 1][ra] = a0.y;
        As[ka + 2][ra] = a0.z; As[ka + 3][ra] = a0.w;
        As[ka + 16][ra] = a1.x; As[ka + 17][ra] = a1.y;
        As[ka + 18][ra] = a1.z; As[ka + 19][ra] = a1.w;
        *(float4*)&Bs[rb0     ][cb] = b0;
        *(float4*)&Bs[rb0 +  8][cb] = b1;
        *(float4*)&Bs[rb0 + 16][cb] = b2;
        *(float4*)&Bs[rb0 + 24][cb] = b3;
        __syncthreads();

#pragma unroll
        for (int kk = 0; kk < 32; ++kk) {
            float4 av  = *(const float4*)&As[kk][ty * 4];
            float4 bv0 = *(const float4*)&Bs[kk][tx * 8];
            float4 bv1 = *(const float4*)&Bs[kk][tx * 8 + 4];
            float a[4] = {av.x, av.y, av.z, av.w};
            float b[8] = {bv0.x, bv0.y, bv0.z, bv0.w,
                          bv1.x, bv1.y, bv1.z, bv1.w};
#pragma unroll
            for (int i = 0; i < 4; ++i)
#pragma unroll
                for (int j = 0; j < 8; ++j)
                    acc[i][j] = fmaf(a[i], b[j], acc[i][j]);
        }
    }

#pragma unroll
    for (int i = 0; i < 4; ++i) {
        int r = ty * 4 + i;
        int sid = s_sid[r];
        if (sid < 0) continue;
        float w = s_w[r];
        float4 o0, o1;
        float* ov0 = (float*)&o0;
        float* ov1 = (float*)&o1;
#pragma unroll
        for (int j = 0; j < 4; ++j) {
            int c = n0 + tx * 8 + j;
            ov0[j] = w * (acc[i][j] + bdn[e * kD + c]);
        }
#pragma unroll
        for (int j = 4; j < 8; ++j) {
            int c = n0 + tx * 8 + j;
            ov1[j - 4] = w * (acc[i][j] + bdn[e * kD + c]);
        }
        float* dst = g_partial + (size_t)sid * kD + n0 + tx * 8;
        *(float4*)dst       = o0;
        *(float4*)(dst + 4) = o1;
    }
}

// ---------------- kernel 4: combine the two expert partials per token ----
__global__ void moe_combine_kernel(float* __restrict__ out) {
    size_t idx = (size_t)blockIdx.x * blockDim.x + threadIdx.x; // float4 idx
    // total float4 = kT * kD / 4 = 2,097,152 (grid sized exactly)
    size_t t = idx >> 9;          // / (kD/4)
    size_t c = idx & 511;         // % (kD/4)
    const float4* p = (const float4*)g_partial;
    float4 a = p[(2 * t) * 512 + c];
    float4 b = p[(2 * t + 1) * 512 + c];
    float4 o = make_float4(a.x + b.x, a.y + b.y, a.z + b.z, a.w + b.w);
    ((float4*)out)[idx] = o;
}

// ---------------- kernel 5: expert loads + aux loss (deterministic) ------
__global__ void moe_loss_kernel(float* __restrict__ out_tail) {
    __shared__ float red[256];
    __shared__ float means[kE];
    float s[kE];
#pragma unroll
    for (int e = 0; e < kE; ++e) s[e] = 0.f;
    for (int t = threadIdx.x; t < kT; t += 256) {
        const float* p = g_probs + (size_t)t * kE;
#pragma unroll
        for (int e = 0; e < kE; ++e) s[e] += p[e];
    }
    for (int e = 0; e < kE; ++e) {
        red[threadIdx.x] = s[e];
        __syncthreads();
        for (int off = 128; off > 0; off >>= 1) {
            if (threadIdx.x < off) red[threadIdx.x] += red[threadIdx.x + off];
            __syncthreads();
        }
        if (threadIdx.x == 0) means[e] = red[0] / (float)kT;
        __syncthreads();
    }
    if (threadIdx.x == 0) {
        float loss = 0.f;
        for (int e = 0; e < kE; ++e) {
            float frac = (float)g_counts[e] / (float)(kT * 2);
            out_tail[e] = frac;                 // expert_loads
            loss += frac * means[e];
        }
        out_tail[kE] = kAux * (float)kE * loss; // load_balancing_loss
    }
}

// ---------------- launch ----------------
extern "C" void kernel_launch(void* const* d_in, const int* in_sizes, int n_in,
                              void* d_out, int out_size) {
    const float* x   = (const float*)d_in[0];
    const float* rw  = (const float*)d_in[1];
    const float* rb  = (const float*)d_in[2];
    const float* wgu = (const float*)d_in[3];
    const float* bgu = (const float*)d_in[4];
    const float* wdn = (const float*)d_in[5];
    const float* bdn = (const float*)d_in[6];
    float* out = (float*)d_out;

    moe_init_kernel<<<1, 32>>>();
    moe_router_kernel<<<(kT * 32) / 256, 256>>>(x, rw, rb);

    // worst case: one expert owns all 4096 tokens -> 64 M-tiles per expert
    dim3 g1(kF / 64, kE * 64);   // (32, 512)
    moe_gate_up_kernel<<<g1, 256>>>(x, wgu, bgu);

    dim3 g2(kD / 128, kE * 64);  // (16, 512)
    moe_down_kernel<<<g2, 256>>>(wdn, bdn);

    moe_combine_kernel<<<(kT * kD / 4) / 256, 256>>>(out);
    moe_loss_kernel<<<1, 256>>>(out + (size_t)kT * kD);
}